// round 2
// baseline (speedup 1.0000x reference)
#include <cuda_runtime.h>

// ---------------- problem constants ----------------
#define N_PATCH   40000
#define GRP       4
#define DIM       400          // 16*5*5
#define KC        64           // clusters
#define EPOCHS    10
#define ROWSTRIDE 1600         // GRP*DIM floats per patch row

// assign-kernel tiling
#define TM   128               // patches per CTA
#define DK   40                // k-chunk (400 = 10*40)
#define APAD 44                // padded smem row (16B aligned, conflict-friendly)

// sum-kernel partition (D split in 2 halves -> 2 CTAs/SM)
#define SUM_CTAS 37
#define PPC      1082          // ceil(40000/37)
#define HCOLS    200

// ---------------- device state ----------------
__device__ float g_centroids[GRP * KC * DIM];
__device__ float g_c2[GRP * KC];
__device__ int   g_labels[GRP * N_PATCH];
__device__ float g_sums[GRP * KC * DIM];
__device__ float g_counts[GRP * KC];

// ---------------- packed fp32x2 helpers ----------------
__device__ __forceinline__ void ffma2(unsigned long long& d,
                                      unsigned long long a,
                                      unsigned long long b) {
    asm("fma.rn.f32x2 %0, %1, %2, %0;" : "+l"(d) : "l"(a), "l"(b));
}
__device__ __forceinline__ float unpack_sum(unsigned long long v) {
    float lo, hi;
    asm("mov.b64 {%0, %1}, %2;" : "=f"(lo), "=f"(hi) : "l"(v));
    return lo + hi;
}

// ---------------- kernels ----------------
__global__ void copy_init_kernel(const float* __restrict__ cin) {
    int i = blockIdx.x * blockDim.x + threadIdx.x;
    if (i < GRP * KC * DIM) g_centroids[i] = cin[i];
}

// initial prep only (epoch 0): c2 = 0.5*||c||^2, zero sums + counts
__global__ void prep_kernel() {
    int b = blockIdx.x;                 // g*KC + k
    const float* c = &g_centroids[b * DIM];
    float s = 0.f;
    for (int d = threadIdx.x; d < DIM; d += 128) {
        float v = c[d];
        s += v * v;
        g_sums[b * DIM + d] = 0.f;
    }
#pragma unroll
    for (int o = 16; o; o >>= 1) s += __shfl_down_sync(0xffffffffu, s, o);
    __shared__ float ws[4];
    if ((threadIdx.x & 31) == 0) ws[threadIdx.x >> 5] = s;
    __syncthreads();
    if (threadIdx.x == 0) {
        g_c2[b] = 0.5f * (ws[0] + ws[1] + ws[2] + ws[3]);
        g_counts[b] = 0.f;
    }
}

// scores = C . P^T tile (128 patches x 64 clusters, K=400), packed f32x2 FMA,
// fused argmax -> labels
__global__ void __launch_bounds__(256) assign_kernel(const float* __restrict__ patches) {
    __shared__ float smem[TM * APAD + KC * APAD];   // union: tiles OR Cs[128][65]
    __shared__ float c2s[KC];
    float* As = smem;
    float* Bs = smem + TM * APAD;

    const int g    = blockIdx.y;
    const int row0 = blockIdx.x * TM;
    const int tid  = threadIdx.x;
    const int tx   = tid & 15;
    const int ty   = tid >> 4;

    if (tid < KC) c2s[tid] = g_c2[g * KC + tid];

    // packed accumulators: lo = even-k partial sum, hi = odd-k partial sum
    unsigned long long acc[8][4];
#pragma unroll
    for (int i = 0; i < 8; i++)
#pragma unroll
        for (int j = 0; j < 4; j++) acc[i][j] = 0ULL;

    const float* cbase = &g_centroids[g * KC * DIM];

    for (int kk = 0; kk < DIM; kk += DK) {
        // load A chunk: 128 rows x 40 floats = 1280 float4
#pragma unroll
        for (int l = 0; l < 5; l++) {
            int idx = tid + l * 256;
            int r = idx / 10, c = idx % 10;
            int n = row0 + r;
            float4 v = make_float4(0.f, 0.f, 0.f, 0.f);
            if (n < N_PATCH)
                v = *(const float4*)&patches[(size_t)n * ROWSTRIDE + g * DIM + kk + c * 4];
            *(float4*)&As[r * APAD + c * 4] = v;
        }
        // load B chunk: 64 rows x 40 floats = 640 float4
        for (int idx = tid; idx < 640; idx += 256) {
            int r = idx / 10, c = idx % 10;
            *(float4*)&Bs[r * APAD + c * 4] =
                *(const float4*)&cbase[r * DIM + kk + c * 4];
        }
        __syncthreads();

#pragma unroll
        for (int k = 0; k < DK; k += 4) {
            ulonglong2 a2[8], b2[4];
#pragma unroll
            for (int i = 0; i < 8; i++)
                a2[i] = *(const ulonglong2*)&As[(ty + 16 * i) * APAD + k];
#pragma unroll
            for (int j = 0; j < 4; j++)
                b2[j] = *(const ulonglong2*)&Bs[(tx + 16 * j) * APAD + k];
#pragma unroll
            for (int i = 0; i < 8; i++)
#pragma unroll
                for (int j = 0; j < 4; j++) {
                    ffma2(acc[i][j], a2[i].x, b2[j].x);
                    ffma2(acc[i][j], a2[i].y, b2[j].y);
                }
        }
        __syncthreads();
    }

    // epilogue: stage scores - c2 into smem, then per-row argmax (first-max ties)
    float* Cs = smem;   // [128][65]
#pragma unroll
    for (int i = 0; i < 8; i++)
#pragma unroll
        for (int j = 0; j < 4; j++)
            Cs[(ty + 16 * i) * 65 + (tx + 16 * j)] =
                unpack_sum(acc[i][j]) - c2s[tx + 16 * j];
    __syncthreads();

    if (tid < TM) {
        int n = row0 + tid;
        if (n < N_PATCH) {
            const float* row = &Cs[tid * 65];
            float best = row[0];
            int bi = 0;
#pragma unroll
            for (int k2 = 1; k2 < KC; k2++) {
                float v = row[k2];
                if (v > best) { best = v; bi = k2; }
            }
            g_labels[g * N_PATCH + n] = bi;
        }
    }
}

// per-CTA K x 200 partial sums in dynamic smem (D split across blockIdx.z),
// vector red.global flush
__global__ void sum_kernel(const float* __restrict__ patches) {
    extern __shared__ float ssum[];                 // KC*HCOLS sums + KC counts
    float* acc = ssum;
    float* cnt = ssum + KC * HCOLS;
    const int g    = blockIdx.y;
    const int half = blockIdx.z;
    const int s    = blockIdx.x;
    const int tid  = threadIdx.x;

    for (int i = tid; i < KC * HCOLS; i += 256) acc[i] = 0.f;
    if (tid < KC) cnt[tid] = 0.f;
    __syncthreads();

    const int start = s * PPC;
    const int end   = min(start + PPC, N_PATCH);
    const int* lbl  = &g_labels[g * N_PATCH];
    const bool lane_ok = (tid < HCOLS);

    for (int nb = start; nb < end; nb += 8) {
        int nu = min(8, end - nb);
        int   l[8];
        float v[8];
#pragma unroll
        for (int u = 0; u < 8; u++) {
            bool ok = (u < nu);
            int nn = ok ? (nb + u) : start;
            l[u] = lbl[nn];
            v[u] = (ok && lane_ok)
                 ? patches[(size_t)nn * ROWSTRIDE + g * DIM + half * HCOLS + tid]
                 : 0.f;
        }
#pragma unroll
        for (int u = 0; u < 8; u++) {
            if (u < nu) {
                if (lane_ok) acc[l[u] * HCOLS + tid] += v[u];
                if (tid == 255 && half == 0) cnt[l[u]] += 1.f;
            }
        }
    }
    __syncthreads();

    // vector atomic flush: 4 floats per red.global
    for (int i4 = tid * 4; i4 < KC * HCOLS; i4 += 1024) {
        int k = i4 / HCOLS, c = i4 % HCOLS;
        float4 vv = *(const float4*)&acc[i4];
        float* dst = &g_sums[(size_t)g * KC * DIM + k * DIM + half * HCOLS + c];
        asm volatile("red.global.add.v4.f32 [%0], {%1, %2, %3, %4};"
                     :: "l"(dst), "f"(vv.x), "f"(vv.y), "f"(vv.z), "f"(vv.w)
                     : "memory");
    }
    if (half == 0 && tid < KC) atomicAdd(&g_counts[g * KC + tid], cnt[tid]);
}

// new centroids = sums / max(count,1); zero cluster k if empty in ANY group.
// Also fused prep for NEXT epoch: c2 = 0.5*||c_new||^2, zero sums + counts.
__global__ void finalize_kernel(float* out) {
    int b = blockIdx.x;            // g*KC + k
    int k = b % KC;
    __shared__ float denom_s;
    __shared__ int   bad_s;
    __shared__ float ws[4];
    if (threadIdx.x == 0) {
        bool bad = false;
        for (int gg = 0; gg < GRP; gg++)
            if (g_counts[gg * KC + k] == 0.f) bad = true;
        float c = g_counts[b];
        denom_s = (c == 0.f) ? 1.f : c;
        bad_s = bad ? 1 : 0;
    }
    __syncthreads();
    float denom = denom_s;
    int bad = bad_s;
    float s = 0.f;
    for (int d = threadIdx.x; d < DIM; d += 128) {
        float v = bad ? 0.f : (g_sums[b * DIM + d] / denom);
        g_centroids[b * DIM + d] = v;
        if (out) out[b * DIM + d] = v;
        s += v * v;
        g_sums[b * DIM + d] = 0.f;                 // prep for next epoch
    }
#pragma unroll
    for (int o = 16; o; o >>= 1) s += __shfl_down_sync(0xffffffffu, s, o);
    if ((threadIdx.x & 31) == 0) ws[threadIdx.x >> 5] = s;
    __syncthreads();
    if (threadIdx.x == 0) {
        g_c2[b] = 0.5f * (ws[0] + ws[1] + ws[2] + ws[3]);
        g_counts[b] = 0.f;                         // prep for next epoch
    }
}

// ---------------- launch ----------------
extern "C" void kernel_launch(void* const* d_in, const int* in_sizes, int n_in,
                              void* d_out, int out_size) {
    const float* patches = (const float*)d_in[0];
    const float* cinit   = (const float*)d_in[1];
    float* out = (float*)d_out;

    const int sum_smem = (KC * HCOLS + KC) * (int)sizeof(float);   // 51,456 B
    cudaFuncSetAttribute(sum_kernel, cudaFuncAttributeMaxDynamicSharedMemorySize, sum_smem);

    copy_init_kernel<<<(GRP * KC * DIM + 255) / 256, 256>>>(cinit);
    prep_kernel<<<GRP * KC, 128>>>();

    for (int e = 0; e < EPOCHS; e++) {
        assign_kernel<<<dim3((N_PATCH + TM - 1) / TM, GRP), 256>>>(patches);
        sum_kernel<<<dim3(SUM_CTAS, GRP, 2), 256, sum_smem>>>(patches);
        finalize_kernel<<<GRP * KC, 128>>>(e == EPOCHS - 1 ? out : nullptr);
    }
}

// round 3
// speedup vs baseline: 1.3784x; 1.3784x over previous
#include <cuda_runtime.h>

// ---------------- problem constants ----------------
#define N_PATCH   40000
#define GRP       4
#define DIM       400          // 16*5*5
#define KC        64           // clusters
#define EPOCHS    10
#define ROWSTRIDE 1600         // GRP*DIM floats per patch row

// assign-kernel tiling
#define TM   128               // patches per CTA
#define DK   40                // k-chunk (400 = 10*40)
#define APAD 44                // padded smem row (16B aligned for float4 stores)

// sum-kernel partition (R1 proven config: full D per CTA, 2 CTAs/SM)
#define SUM_CTAS 74
#define PPC      541           // ceil(40000/74)

// ---------------- device state ----------------
__device__ float g_centroids[GRP * KC * DIM];
__device__ float g_c2[GRP * KC];
__device__ int   g_labels[GRP * N_PATCH];
__device__ float g_sums[GRP * KC * DIM];
__device__ float g_counts[GRP * KC];

// ---------------- packed fp32x2 helpers ----------------
__device__ __forceinline__ void ffma2(unsigned long long& d,
                                      unsigned long long a,
                                      unsigned long long b) {
    asm("fma.rn.f32x2 %0, %1, %2, %0;" : "+l"(d) : "l"(a), "l"(b));
}
__device__ __forceinline__ float unpack_sum(unsigned long long v) {
    float lo, hi;
    asm("mov.b64 {%0, %1}, %2;" : "=f"(lo), "=f"(hi) : "l"(v));
    return lo + hi;
}

// ---------------- kernels ----------------
__global__ void copy_init_kernel(const float* __restrict__ cin) {
    int i = blockIdx.x * blockDim.x + threadIdx.x;
    if (i < GRP * KC * DIM) g_centroids[i] = cin[i];
}

// initial prep only (epoch 0): c2 = 0.5*||c||^2, zero sums + counts
__global__ void prep_kernel() {
    int b = blockIdx.x;                 // g*KC + k
    const float* c = &g_centroids[b * DIM];
    float s = 0.f;
    for (int d = threadIdx.x; d < DIM; d += 128) {
        float v = c[d];
        s += v * v;
        g_sums[b * DIM + d] = 0.f;
    }
#pragma unroll
    for (int o = 16; o; o >>= 1) s += __shfl_down_sync(0xffffffffu, s, o);
    __shared__ float ws[4];
    if ((threadIdx.x & 31) == 0) ws[threadIdx.x >> 5] = s;
    __syncthreads();
    if (threadIdx.x == 0) {
        g_c2[b] = 0.5f * (ws[0] + ws[1] + ws[2] + ws[3]);
        g_counts[b] = 0.f;
    }
}

// scores = C . P^T tile (128 patches x 64 clusters, K=400), packed f32x2 FMA
// (k-pairs in lo/hi), fused argmax -> labels. Register budget ~110 -> 2 CTAs/SM.
__global__ void __launch_bounds__(256, 2) assign_kernel(const float* __restrict__ patches) {
    __shared__ float smem[TM * APAD + KC * APAD];   // union: tiles OR Cs[128][65]
    __shared__ float c2s[KC];
    float* As = smem;
    float* Bs = smem + TM * APAD;

    const int g    = blockIdx.y;
    const int row0 = blockIdx.x * TM;
    const int tid  = threadIdx.x;
    const int tx   = tid & 15;
    const int ty   = tid >> 4;

    if (tid < KC) c2s[tid] = g_c2[g * KC + tid];

    // packed accumulators: lo = even-k partial, hi = odd-k partial
    unsigned long long acc[8][4];
#pragma unroll
    for (int i = 0; i < 8; i++)
#pragma unroll
        for (int j = 0; j < 4; j++) acc[i][j] = 0ULL;

    const float* cbase = &g_centroids[g * KC * DIM];

    for (int kk = 0; kk < DIM; kk += DK) {
        // load A chunk: 128 rows x 40 floats = 1280 float4
#pragma unroll
        for (int l = 0; l < 5; l++) {
            int idx = tid + l * 256;
            int r = idx / 10, c = idx % 10;
            int n = row0 + r;
            float4 v = make_float4(0.f, 0.f, 0.f, 0.f);
            if (n < N_PATCH)
                v = *(const float4*)&patches[(size_t)n * ROWSTRIDE + g * DIM + kk + c * 4];
            *(float4*)&As[r * APAD + c * 4] = v;
        }
        // load B chunk: 64 rows x 40 floats = 640 float4
        for (int idx = tid; idx < 640; idx += 256) {
            int r = idx / 10, c = idx % 10;
            *(float4*)&Bs[r * APAD + c * 4] =
                *(const float4*)&cbase[r * DIM + kk + c * 4];
        }
        __syncthreads();

#pragma unroll
        for (int k = 0; k < DK; k += 2) {
            unsigned long long a2[8], b2[4];
#pragma unroll
            for (int i = 0; i < 8; i++)
                a2[i] = *(const unsigned long long*)&As[(ty + 16 * i) * APAD + k];
#pragma unroll
            for (int j = 0; j < 4; j++)
                b2[j] = *(const unsigned long long*)&Bs[(tx + 16 * j) * APAD + k];
#pragma unroll
            for (int i = 0; i < 8; i++)
#pragma unroll
                for (int j = 0; j < 4; j++)
                    ffma2(acc[i][j], a2[i], b2[j]);
        }
        __syncthreads();
    }

    // epilogue: stage scores - c2 into smem, then per-row argmax (first-max ties)
    float* Cs = smem;   // [128][65]
#pragma unroll
    for (int i = 0; i < 8; i++)
#pragma unroll
        for (int j = 0; j < 4; j++)
            Cs[(ty + 16 * i) * 65 + (tx + 16 * j)] =
                unpack_sum(acc[i][j]) - c2s[tx + 16 * j];
    __syncthreads();

    if (tid < TM) {
        int n = row0 + tid;
        if (n < N_PATCH) {
            const float* row = &Cs[tid * 65];
            float best = row[0];
            int bi = 0;
#pragma unroll
            for (int k2 = 1; k2 < KC; k2++) {
                float v = row[k2];
                if (v > best) { best = v; bi = k2; }
            }
            g_labels[g * N_PATCH + n] = bi;
        }
    }
}

// per-CTA K*D partial sums in dynamic smem, atomic flush (R1 proven version)
__global__ void sum_kernel(const float* __restrict__ patches) {
    extern __shared__ float ssum[];                 // KC*DIM sums + KC counts
    float* acc = ssum;
    float* cnt = ssum + KC * DIM;
    const int g   = blockIdx.y;
    const int s   = blockIdx.x;
    const int tid = threadIdx.x;

    for (int i = tid; i < KC * DIM; i += 256) acc[i] = 0.f;
    if (tid < KC) cnt[tid] = 0.f;
    __syncthreads();

    const int start = s * PPC;
    const int end   = min(start + PPC, N_PATCH);
    const int* lbl  = &g_labels[g * N_PATCH];

    for (int nb = start; nb < end; nb += 8) {
        int nu = min(8, end - nb);
        int   l[8];
        float v0[8], v1[8];
#pragma unroll
        for (int u = 0; u < 8; u++) {
            bool ok = (u < nu);
            int nn = ok ? (nb + u) : start;
            l[u] = lbl[nn];
            const float* p = &patches[(size_t)nn * ROWSTRIDE + g * DIM];
            v0[u] = ok ? p[tid] : 0.f;
            v1[u] = (ok && tid < DIM - 256) ? p[256 + tid] : 0.f;
        }
#pragma unroll
        for (int u = 0; u < 8; u++) {
            if (u < nu) {
                acc[l[u] * DIM + tid] += v0[u];
                if (tid < DIM - 256) acc[l[u] * DIM + 256 + tid] += v1[u];
                if (tid == 0) cnt[l[u]] += 1.f;
            }
        }
    }
    __syncthreads();

    for (int i = tid; i < KC * DIM; i += 256)
        atomicAdd(&g_sums[(size_t)g * KC * DIM + i], acc[i]);
    if (tid < KC) atomicAdd(&g_counts[g * KC + tid], cnt[tid]);
}

// new centroids = sums / max(count,1); zero cluster k if empty in ANY group.
// Fused prep for NEXT epoch: c2 = 0.5*||c_new||^2, zero sums + counts.
__global__ void finalize_kernel(float* out) {
    int b = blockIdx.x;            // g*KC + k
    int k = b % KC;
    __shared__ float denom_s;
    __shared__ int   bad_s;
    __shared__ float ws[4];
    if (threadIdx.x == 0) {
        bool bad = false;
        for (int gg = 0; gg < GRP; gg++)
            if (g_counts[gg * KC + k] == 0.f) bad = true;
        float c = g_counts[b];
        denom_s = (c == 0.f) ? 1.f : c;
        bad_s = bad ? 1 : 0;
    }
    __syncthreads();
    float denom = denom_s;
    int bad = bad_s;
    float s = 0.f;
    for (int d = threadIdx.x; d < DIM; d += 128) {
        float v = bad ? 0.f : (g_sums[b * DIM + d] / denom);
        g_centroids[b * DIM + d] = v;
        if (out) out[b * DIM + d] = v;
        s += v * v;
        g_sums[b * DIM + d] = 0.f;                 // prep next epoch
    }
#pragma unroll
    for (int o = 16; o; o >>= 1) s += __shfl_down_sync(0xffffffffu, s, o);
    if ((threadIdx.x & 31) == 0) ws[threadIdx.x >> 5] = s;
    __syncthreads();
    if (threadIdx.x == 0) {
        g_c2[b] = 0.5f * (ws[0] + ws[1] + ws[2] + ws[3]);
        g_counts[b] = 0.f;                         // prep next epoch
    }
}

// ---------------- launch ----------------
extern "C" void kernel_launch(void* const* d_in, const int* in_sizes, int n_in,
                              void* d_out, int out_size) {
    const float* patches = (const float*)d_in[0];
    const float* cinit   = (const float*)d_in[1];
    float* out = (float*)d_out;

    const int sum_smem = (KC * DIM + KC) * (int)sizeof(float);   // 102,656 B
    cudaFuncSetAttribute(sum_kernel, cudaFuncAttributeMaxDynamicSharedMemorySize, sum_smem);

    copy_init_kernel<<<(GRP * KC * DIM + 255) / 256, 256>>>(cinit);
    prep_kernel<<<GRP * KC, 128>>>();

    for (int e = 0; e < EPOCHS; e++) {
        assign_kernel<<<dim3((N_PATCH + TM - 1) / TM, GRP), 256>>>(patches);
        sum_kernel<<<dim3(SUM_CTAS, GRP), 256, sum_smem>>>(patches);
        finalize_kernel<<<GRP * KC, 128>>>(e == EPOCHS - 1 ? out : nullptr);
    }
}

// round 4
// speedup vs baseline: 1.4000x; 1.0157x over previous
#include <cuda_runtime.h>

// ---------------- problem constants ----------------
#define N_PATCH   40000
#define GRP       4
#define DIM       400          // 16*5*5
#define KC        64           // clusters
#define EPOCHS    10
#define ROWSTRIDE 1600         // GRP*DIM floats per patch row

// assign-kernel tiling
#define TM   128               // patches per CTA
#define DK   40                // k-chunk (400 = 10*40)
#define ASTR 129               // A smem stride in float2 (k-major), conflict-tuned
#define BSTR 65                // B smem stride in float2 (k-major), conflict-tuned

// sum-kernel partition
#define SUM_CTAS 74
#define PPC      541           // ceil(40000/74)
#define UB       16            // patch unroll

// ---------------- device state ----------------
__device__ float g_centroids[GRP * KC * DIM];
__device__ float g_c2[GRP * KC];
__device__ int   g_labels[GRP * N_PATCH];
__device__ float g_sums[GRP * KC * DIM];
__device__ float g_counts[GRP * KC];

// ---------------- packed fp32x2 helpers ----------------
__device__ __forceinline__ void ffma2(unsigned long long& d,
                                      unsigned long long a,
                                      unsigned long long b) {
    asm("fma.rn.f32x2 %0, %1, %2, %0;" : "+l"(d) : "l"(a), "l"(b));
}
__device__ __forceinline__ float unpack_sum(unsigned long long v) {
    float lo, hi;
    asm("mov.b64 {%0, %1}, %2;" : "=f"(lo), "=f"(hi) : "l"(v));
    return lo + hi;
}

// ---------------- kernels ----------------
__global__ void copy_init_kernel(const float* __restrict__ cin) {
    int i = blockIdx.x * blockDim.x + threadIdx.x;
    if (i < GRP * KC * DIM) g_centroids[i] = cin[i];
}

// initial prep only (epoch 0): c2 = 0.5*||c||^2, zero sums + counts
__global__ void prep_kernel() {
    int b = blockIdx.x;                 // g*KC + k
    const float* c = &g_centroids[b * DIM];
    float s = 0.f;
    for (int d = threadIdx.x; d < DIM; d += 128) {
        float v = c[d];
        s += v * v;
        g_sums[b * DIM + d] = 0.f;
    }
#pragma unroll
    for (int o = 16; o; o >>= 1) s += __shfl_down_sync(0xffffffffu, s, o);
    __shared__ float ws[4];
    if ((threadIdx.x & 31) == 0) ws[threadIdx.x >> 5] = s;
    __syncthreads();
    if (threadIdx.x == 0) {
        g_c2[b] = 0.5f * (ws[0] + ws[1] + ws[2] + ws[3]);
        g_counts[b] = 0.f;
    }
}

// scores = C . P^T (128 patches x 64 clusters, K=400), k-major packed-float2
// smem (conflict-free operand LDS), f32x2 FMA, fused argmax -> labels.
__global__ void __launch_bounds__(256, 2) assign_kernel(const float* __restrict__ patches) {
    // union: staging tiles (A: 2580 f2 + B: 1300 f2 = 7760 floats) OR Cs[128][65]
    __shared__ float smem[TM * 65];
    __shared__ float c2s[KC];
    float2* As2 = (float2*)smem;                 // [DK/2][ASTR]
    float2* Bs2 = (float2*)(smem + 2 * (DK / 2) * ASTR);   // [DK/2][BSTR]

    const int g    = blockIdx.y;
    const int row0 = blockIdx.x * TM;
    const int tid  = threadIdx.x;
    const int tx   = tid & 15;
    const int ty   = tid >> 4;

    if (tid < KC) c2s[tid] = g_c2[g * KC + tid];

    // packed accumulators: lo = even-k partial, hi = odd-k partial
    unsigned long long acc[8][4];
#pragma unroll
    for (int i = 0; i < 8; i++)
#pragma unroll
        for (int j = 0; j < 4; j++) acc[i][j] = 0ULL;

    const float* cbase = &g_centroids[g * KC * DIM];

    for (int kk = 0; kk < DIM; kk += DK) {
        // stage A chunk k-major: 128 rows x 40 floats (coalesced LDG.128)
#pragma unroll
        for (int l = 0; l < 5; l++) {
            int idx = tid + l * 256;
            int r = idx / 10, c = idx % 10;
            int n = row0 + r;
            float4 v = make_float4(0.f, 0.f, 0.f, 0.f);
            if (n < N_PATCH)
                v = *(const float4*)&patches[(size_t)n * ROWSTRIDE + g * DIM + kk + c * 4];
            As2[(2 * c + 0) * ASTR + r] = make_float2(v.x, v.y);
            As2[(2 * c + 1) * ASTR + r] = make_float2(v.z, v.w);
        }
        // stage B chunk k-major: 64 rows x 40 floats
        for (int idx = tid; idx < 640; idx += 256) {
            int r = idx / 10, c = idx % 10;
            float4 v = *(const float4*)&cbase[r * DIM + kk + c * 4];
            Bs2[(2 * c + 0) * BSTR + r] = make_float2(v.x, v.y);
            Bs2[(2 * c + 1) * BSTR + r] = make_float2(v.z, v.w);
        }
        __syncthreads();

#pragma unroll
        for (int k2 = 0; k2 < DK / 2; k2++) {
            unsigned long long a2[8], b2[4];
#pragma unroll
            for (int i = 0; i < 8; i++)
                a2[i] = *(const unsigned long long*)&As2[k2 * ASTR + ty + 16 * i];
#pragma unroll
            for (int j = 0; j < 4; j++)
                b2[j] = *(const unsigned long long*)&Bs2[k2 * BSTR + tx + 16 * j];
#pragma unroll
            for (int i = 0; i < 8; i++)
#pragma unroll
                for (int j = 0; j < 4; j++)
                    ffma2(acc[i][j], a2[i], b2[j]);
        }
        __syncthreads();
    }

    // epilogue: stage scores - c2 into smem, then per-row argmax (first-max ties)
    float* Cs = smem;   // [128][65]
#pragma unroll
    for (int i = 0; i < 8; i++)
#pragma unroll
        for (int j = 0; j < 4; j++)
            Cs[(ty + 16 * i) * 65 + (tx + 16 * j)] =
                unpack_sum(acc[i][j]) - c2s[tx + 16 * j];
    __syncthreads();

    if (tid < TM) {
        int n = row0 + tid;
        if (n < N_PATCH) {
            const float* row = &Cs[tid * 65];
            float best = row[0];
            int bi = 0;
#pragma unroll
            for (int k2 = 1; k2 < KC; k2++) {
                float v = row[k2];
                if (v > best) { best = v; bi = k2; }
            }
            g_labels[g * N_PATCH + n] = bi;
        }
    }
}

// per-CTA K*D partial sums in dynamic smem, 16-patch unroll for MLP, atomic flush
__global__ void sum_kernel(const float* __restrict__ patches) {
    extern __shared__ float ssum[];                 // KC*DIM sums + KC counts
    float* acc = ssum;
    float* cnt = ssum + KC * DIM;
    const int g   = blockIdx.y;
    const int s   = blockIdx.x;
    const int tid = threadIdx.x;

    for (int i = tid; i < KC * DIM; i += 256) acc[i] = 0.f;
    if (tid < KC) cnt[tid] = 0.f;
    __syncthreads();

    const int start = s * PPC;
    const int end   = min(start + PPC, N_PATCH);
    const int* lbl  = &g_labels[g * N_PATCH];

    for (int nb = start; nb < end; nb += UB) {
        int nu = min(UB, end - nb);
        int   l[UB];
        float v0[UB], v1[UB];
#pragma unroll
        for (int u = 0; u < UB; u++) {
            bool ok = (u < nu);
            int nn = ok ? (nb + u) : start;
            l[u] = lbl[nn];
            const float* p = &patches[(size_t)nn * ROWSTRIDE + g * DIM];
            v0[u] = ok ? p[tid] : 0.f;
            v1[u] = (ok && tid < DIM - 256) ? p[256 + tid] : 0.f;
        }
#pragma unroll
        for (int u = 0; u < UB; u++) {
            if (u < nu) {
                acc[l[u] * DIM + tid] += v0[u];
                if (tid < DIM - 256) acc[l[u] * DIM + 256 + tid] += v1[u];
                if (tid == 0) cnt[l[u]] += 1.f;
            }
        }
    }
    __syncthreads();

    for (int i = tid; i < KC * DIM; i += 256)
        atomicAdd(&g_sums[(size_t)g * KC * DIM + i], acc[i]);
    if (tid < KC) atomicAdd(&g_counts[g * KC + tid], cnt[tid]);
}

// new centroids = sums / max(count,1); zero cluster k if empty in ANY group.
// Fused prep for NEXT epoch: c2 = 0.5*||c_new||^2, zero sums + counts.
__global__ void finalize_kernel(float* out) {
    int b = blockIdx.x;            // g*KC + k
    int k = b % KC;
    __shared__ float denom_s;
    __shared__ int   bad_s;
    __shared__ float ws[4];
    if (threadIdx.x == 0) {
        bool bad = false;
        for (int gg = 0; gg < GRP; gg++)
            if (g_counts[gg * KC + k] == 0.f) bad = true;
        float c = g_counts[b];
        denom_s = (c == 0.f) ? 1.f : c;
        bad_s = bad ? 1 : 0;
    }
    __syncthreads();
    float denom = denom_s;
    int bad = bad_s;
    float s = 0.f;
    for (int d = threadIdx.x; d < DIM; d += 128) {
        float v = bad ? 0.f : (g_sums[b * DIM + d] / denom);
        g_centroids[b * DIM + d] = v;
        if (out) out[b * DIM + d] = v;
        s += v * v;
        g_sums[b * DIM + d] = 0.f;                 // prep next epoch
    }
#pragma unroll
    for (int o = 16; o; o >>= 1) s += __shfl_down_sync(0xffffffffu, s, o);
    if ((threadIdx.x & 31) == 0) ws[threadIdx.x >> 5] = s;
    __syncthreads();
    if (threadIdx.x == 0) {
        g_c2[b] = 0.5f * (ws[0] + ws[1] + ws[2] + ws[3]);
        g_counts[b] = 0.f;                         // prep next epoch
    }
}

// ---------------- launch ----------------
extern "C" void kernel_launch(void* const* d_in, const int* in_sizes, int n_in,
                              void* d_out, int out_size) {
    const float* patches = (const float*)d_in[0];
    const float* cinit   = (const float*)d_in[1];
    float* out = (float*)d_out;

    const int sum_smem = (KC * DIM + KC) * (int)sizeof(float);   // 102,656 B
    cudaFuncSetAttribute(sum_kernel, cudaFuncAttributeMaxDynamicSharedMemorySize, sum_smem);

    copy_init_kernel<<<(GRP * KC * DIM + 255) / 256, 256>>>(cinit);
    prep_kernel<<<GRP * KC, 128>>>();

    for (int e = 0; e < EPOCHS; e++) {
        assign_kernel<<<dim3((N_PATCH + TM - 1) / TM, GRP), 256>>>(patches);
        sum_kernel<<<dim3(SUM_CTAS, GRP), 256, sum_smem>>>(patches);
        finalize_kernel<<<GRP * KC, 128>>>(e == EPOCHS - 1 ? out : nullptr);
    }
}